// round 15
// baseline (speedup 1.0000x reference)
#include <cuda_runtime.h>
#include <cuda_bf16.h>
#include <cstdint>

// MaxUnpooling2DMod: out[b, y(idx), x(idx), c] += in[b,h,w,c]
//   in  [8,128,128,64] -> 2^23 floats, out [8,256,256,64] -> 2^25 floats
// decode: out_off = (b << 22) + (idx & ~63) + (lin & 63)
//
// Two streams, zeros FUSED into scatter kernels:
//   stream0: z(0), s(0,zero2), s(2,zero4), s(4,zero6), s(6,-)
//   stream1: z(1), s(1,zero3), s(3,zero5), s(5,zero7), s(7,-)
// Each s: trigger at entry (PDL releases next s early) -> elem loads ->
// zero slab b+2 (untouched, dependency-free; fills the wait window) ->
// griddepcontrol.wait (predecessor completion => my slab's zeros visible) ->
// 2 REDG. Both streams scatter continuously; zero stores ride under the
// atomic drain. 1-grid scatter = 100G atomics/s, 2 concurrent = 150G/s
// (R8/R12 data) -> keeping 2 scatters live ~always is the win.

static constexpr int BLOCK   = 256;
static constexpr int SGRID   = 2048;                     // scatter/fused grids
static constexpr int ZGRID   = 1024;                     // prologue zero grids
static constexpr int SLAB_F4 = (1 << 22) / 4;            // 1,048,576 float4/slab

// Unified kernel: optional scatter of batch b, optional zero of slab zslab.
//  b    >= 0: scatter batch b (grid must be 2048 blocks; 2 elems/thread)
//  zslab>= 0: zero slab zslab (generic grid-stride loop)
__global__ void __launch_bounds__(BLOCK)
unpool_fused(const float* __restrict__ in,
             const int*   __restrict__ idx,
             float*       __restrict__ out,
             int b, int zslab)
{
    // Release this stream's next kernel immediately: everything it does
    // before ITS wait (loads + zeroing an untouched slab) is safe now.
    asm volatile("griddepcontrol.launch_dependents;" ::: "memory");

    const int t = blockIdx.x * BLOCK + threadIdx.x;

    // Scatter loads first (long latency, independent of everything).
    float2 v;  int2 id;  int e0 = 0;
    if (b >= 0) {
        e0 = (b << 20) + (t << 1);                       // 2 consecutive elems
        v  = __ldcs(reinterpret_cast<const float2*>(in)  + (e0 >> 1));
        id = __ldcs(reinterpret_cast<const int2*>(idx)   + (e0 >> 1));
    }

    // Zero stores: untouched slab, no dependency — executes during the wait
    // window below and drains under the atomic phase.
    if (zslab >= 0) {
        float4* o4 = reinterpret_cast<float4*>(out) + (size_t)zslab * SLAB_F4;
        const float4 z = make_float4(0.f, 0.f, 0.f, 0.f);
        const int stride = gridDim.x * BLOCK;
        for (int i = t; i < SLAB_F4; i += stride)
            o4[i] = z;
    }

    // Wait for immediate predecessor completion: my scatter slab's zeros
    // (written by s(b-2) / z(b)) are done and visible.
    asm volatile("griddepcontrol.wait;" ::: "memory");

    if (b >= 0) {
        const int base = b << 22;
        const int c0   = e0 & 63;                        // e0 even
        atomicAdd(out + base + (id.x & ~63) + (c0 + 0), v.x);
        atomicAdd(out + base + (id.y & ~63) + (c0 + 1), v.y);
    }
}

extern "C" void kernel_launch(void* const* d_in, const int* in_sizes, int n_in,
                              void* d_out, int out_size)
{
    const float* in  = (const float*)d_in[0];
    const int*   idx = (const int*)d_in[1];
    float*       out = (float*)d_out;

    // One extra stream + fork/join events (host objects only, created once).
    static cudaStream_t sB = nullptr;
    static cudaEvent_t  evFork = nullptr, evJoin = nullptr;
    if (sB == nullptr) {
        cudaStreamCreateWithFlags(&sB, cudaStreamNonBlocking);
        cudaEventCreateWithFlags(&evFork, cudaEventDisableTiming);
        cudaEventCreateWithFlags(&evJoin, cudaEventDisableTiming);
    }

    cudaLaunchAttribute attrs[1];
    attrs[0].id = cudaLaunchAttributeProgrammaticStreamSerialization;
    attrs[0].val.programmaticStreamSerializationAllowed = 1;

    cudaEventRecord(evFork, 0);
    cudaStreamWaitEvent(sB, evFork, 0);

    cudaLaunchConfig_t cfg = {};
    cfg.blockDim = dim3(BLOCK, 1, 1);

    for (int lane = 0; lane < 2; lane++) {
        cudaStream_t st = (lane == 0) ? (cudaStream_t)0 : sB;
        cfg.stream = st;

        // Prologue: zero slab `lane` (no scatter). First kernel in chain: no attr.
        cfg.gridDim = dim3(ZGRID, 1, 1);
        cfg.attrs = nullptr;  cfg.numAttrs = 0;
        cudaLaunchKernelEx(&cfg, unpool_fused, in, idx, out, -1, lane);

        // Fused chain: scatter b, zero b+2 (except last).
        cfg.gridDim = dim3(SGRID, 1, 1);
        cfg.attrs = attrs;  cfg.numAttrs = 1;
        for (int b = lane; b < 8; b += 2) {
            const int zs = (b + 2 < 8) ? b + 2 : -1;
            cudaLaunchKernelEx(&cfg, unpool_fused, in, idx, out, b, zs);
        }
    }

    cudaEventRecord(evJoin, sB);
    cudaStreamWaitEvent(0, evJoin, 0);
}

// round 16
// speedup vs baseline: 1.0491x; 1.0491x over previous
#include <cuda_runtime.h>
#include <cuda_bf16.h>
#include <cstdint>

// MaxUnpooling2DMod: out[b, y(idx), x(idx), c] += in[b,h,w,c]
//   in  [8,128,128,64] -> 2^23 floats, out [8,256,256,64] -> 2^25 floats
// decode: out_off = (b << 22) + (idx & ~63) + (lin & 63)
//
// 4-stream split: zeros on 2 dedicated streams, scatters on 2 streams.
//   sZ0: z0 z2 z4 z6      sZ1: z1 z3 z5 z7      (plain kernels + events)
//   sS0: s0 s2 s4 s6      sS1: s1 s3 s5 s7      (each s_b waits event(z_b))
// Scatter streams run scatters BACK-TO-BACK (no zero gaps — R12's remaining
// bubble). Zeros ride concurrently in the DRAM/L2-store headroom. Consecutive
// scatters on a stream touch disjoint slabs, so PDL with a mid-kernel trigger
// (after atomic #1) hides each scatter's drain under its successor; no
// griddepcontrol.wait needed (z_b ordering comes from the event edge).

static constexpr int BLOCK = 256;

// ---- zero kernel: 512 blocks x 8 float4 (low SM footprint, ~4us) ----
static constexpr int ZGRID      = 512;
static constexpr int ZTHREADS   = ZGRID * BLOCK;
static constexpr int SLAB_F4    = (1 << 22) / 4;
static constexpr int ZERO_PER_T = SLAB_F4 / ZTHREADS;     // 8

__global__ void __launch_bounds__(BLOCK)
zero_slab_kernel(float* __restrict__ out, int slab)
{
    const int t = blockIdx.x * BLOCK + threadIdx.x;
    float4* o4 = reinterpret_cast<float4*>(out) + (size_t)slab * SLAB_F4;
    const float4 z = make_float4(0.f, 0.f, 0.f, 0.f);
    #pragma unroll
    for (int j = 0; j < ZERO_PER_T; j++)
        o4[t + j * ZTHREADS] = z;
}

// ---- scatter kernel: 2048 blocks x 2 elems, PDL trigger mid-kernel ----
static constexpr int SGRID = 2048;

__global__ void __launch_bounds__(BLOCK)
scatter_kernel(const float* __restrict__ in,
               const int*   __restrict__ idx,
               float*       __restrict__ out,
               int b)
{
    const int t  = blockIdx.x * BLOCK + threadIdx.x;      // 524288 threads
    const int e0 = (b << 20) + (t << 1);                  // 2 elems/thread

    const float2 v  = __ldcs(reinterpret_cast<const float2*>(in)  + (e0 >> 1));
    const int2   id = __ldcs(reinterpret_cast<const int2*>(idx)   + (e0 >> 1));

    const int base = b << 22;
    const int c0   = e0 & 63;

    atomicAdd(out + base + (id.x & ~63) + (c0 + 0), v.x);
    // Successor (disjoint slab) may launch now; our second atomic and the
    // drain of both overlap with its ramp. No wait in the successor — its
    // only real dependency (its slab's zeros) is a normal event edge.
    asm volatile("griddepcontrol.launch_dependents;" ::: "memory");
    atomicAdd(out + base + (id.y & ~63) + (c0 + 1), v.y);
}

extern "C" void kernel_launch(void* const* d_in, const int* in_sizes, int n_in,
                              void* d_out, int out_size)
{
    const float* in  = (const float*)d_in[0];
    const int*   idx = (const int*)d_in[1];
    float*       out = (float*)d_out;

    // Streams/events: host objects only, created once.
    static cudaStream_t sZ0 = nullptr, sZ1 = nullptr, sS1 = nullptr;
    static cudaEvent_t  evFork = nullptr, evZ[8] = {}, evJoin[3] = {};
    if (sZ0 == nullptr) {
        cudaStreamCreateWithFlags(&sZ0, cudaStreamNonBlocking);
        cudaStreamCreateWithFlags(&sZ1, cudaStreamNonBlocking);
        cudaStreamCreateWithFlags(&sS1, cudaStreamNonBlocking);
        cudaEventCreateWithFlags(&evFork, cudaEventDisableTiming);
        for (int i = 0; i < 8; i++)
            cudaEventCreateWithFlags(&evZ[i], cudaEventDisableTiming);
        for (int i = 0; i < 3; i++)
            cudaEventCreateWithFlags(&evJoin[i], cudaEventDisableTiming);
    }

    cudaLaunchAttribute attrs[1];
    attrs[0].id = cudaLaunchAttributeProgrammaticStreamSerialization;
    attrs[0].val.programmaticStreamSerializationAllowed = 1;

    // Fork all side streams off the capture stream (0).
    cudaEventRecord(evFork, 0);
    cudaStreamWaitEvent(sZ0, evFork, 0);
    cudaStreamWaitEvent(sZ1, evFork, 0);
    cudaStreamWaitEvent(sS1, evFork, 0);

    // Zero streams: even slabs on sZ0, odd on sZ1; event after each.
    for (int j = 0; j < 4; j++) {
        const int be = 2 * j, bo = 2 * j + 1;
        zero_slab_kernel<<<ZGRID, BLOCK, 0, sZ0>>>(out, be);
        cudaEventRecord(evZ[be], sZ0);
        zero_slab_kernel<<<ZGRID, BLOCK, 0, sZ1>>>(out, bo);
        cudaEventRecord(evZ[bo], sZ1);
    }

    // Scatter streams: stream 0 takes even batches, sS1 odd. Each scatter
    // gated by its slab's zero event; PDL overlaps consecutive scatters'
    // drains within a stream.
    cudaLaunchConfig_t cfg = {};
    cfg.gridDim  = dim3(SGRID, 1, 1);
    cfg.blockDim = dim3(BLOCK, 1, 1);
    cfg.attrs    = attrs;
    cfg.numAttrs = 1;

    for (int j = 0; j < 4; j++) {
        const int be = 2 * j, bo = 2 * j + 1;
        cudaStreamWaitEvent(0, evZ[be], 0);
        cfg.stream = 0;
        cudaLaunchKernelEx(&cfg, scatter_kernel, in, idx, out, be);

        cudaStreamWaitEvent(sS1, evZ[bo], 0);
        cfg.stream = sS1;
        cudaLaunchKernelEx(&cfg, scatter_kernel, in, idx, out, bo);
    }

    // Join everything back into stream 0.
    cudaEventRecord(evJoin[0], sS1);
    cudaEventRecord(evJoin[1], sZ0);
    cudaEventRecord(evJoin[2], sZ1);
    cudaStreamWaitEvent(0, evJoin[0], 0);
    cudaStreamWaitEvent(0, evJoin[1], 0);
    cudaStreamWaitEvent(0, evJoin[2], 0);
}